// round 2
// baseline (speedup 1.0000x reference)
#include <cuda_runtime.h>
#include <math.h>

#define N_NODES  524288
#define N_EDGES  2097152
#define N_GRAPHS 16384
#define COMP_DIM 3539
#define PROT_DIM 384
#define GNN_HID  64
#define G_EMB    128
#define HID      256
#define K_TOT    (G_EMB + COMP_DIM + PROT_DIM)   /* 4051 */
#define KP       4056                             /* padded K, multiple of 8, %4==0 */
#define INIT_N   (N_GRAPHS * GNN_HID)             /* 1048576: largest init target */

// -------------------- scratch (static device memory; no allocs) --------------------
__device__ float g_dinv[N_NODES];           // deg -> dinv
__device__ float g_s[N_NODES];              // dinv*node_x
__device__ float g_acc1[N_NODES];           // scalar layer-1 aggregation
__device__ float g_h2s[N_NODES * GNN_HID];  // dinv * (x1 @ W2)
__device__ float g_acc2[N_NODES * GNN_HID]; // layer-2 aggregation
__device__ float g_pool[N_GRAPHS * GNN_HID];
__device__ float g_cnt[N_GRAPHS];
__device__ float g_comb[(size_t)N_GRAPHS * KP]; // [16384, 4056] padded combined
__device__ float g_w1p[(size_t)KP * HID];       // padded Wf1 [4056, 256]
__device__ float g_hid[(size_t)N_GRAPHS * HID]; // relu(combined@Wf1+bf1)

// -------------------- kernels --------------------

__global__ void k_init() {
    int i = blockIdx.x * blockDim.x + threadIdx.x;
    if (i < N_NODES) g_dinv[i] = 1.0f;                 // self-loop degree
    if (i < N_GRAPHS * GNN_HID) g_pool[i] = 0.0f;      // grid sized for this (largest)
    if (i < N_GRAPHS) g_cnt[i] = 0.0f;
}

__global__ void k_deg(const int* __restrict__ ei) {
    int e = blockIdx.x * blockDim.x + threadIdx.x;
    if (e < N_EDGES) atomicAdd(&g_dinv[ei[N_EDGES + e]], 1.0f);
}

__global__ void k_dinv(const float* __restrict__ node_x) {
    int i = blockIdx.x * blockDim.x + threadIdx.x;
    if (i >= N_NODES) return;
    float d = rsqrtf(g_dinv[i]);   // deg >= 1 always (self-loop)
    g_dinv[i] = d;
    float s = d * node_x[i];
    g_s[i] = s;
    g_acc1[i] = s;                 // self-loop contribution
}

__global__ void k_scat1(const int* __restrict__ ei) {
    int e = blockIdx.x * blockDim.x + threadIdx.x;
    if (e < N_EDGES) {
        int r = ei[e];
        int c = ei[N_EDGES + e];
        atomicAdd(&g_acc1[c], g_s[r]);
    }
}

// Fused: x1 = relu(dinv*acc1*W1 + b1) ; h2s = dinv * (x1 @ W2); acc2 init = h2s (self-loop)
__global__ __launch_bounds__(256) void k_layer2(const float* __restrict__ W1,
                                                const float* __restrict__ b1,
                                                const float* __restrict__ W2) {
    __shared__ float sW2[GNN_HID * GNN_HID];
    __shared__ float sW1[GNN_HID];
    __shared__ float sb1[GNN_HID];
    __shared__ float sX[8][GNN_HID];

    int tid = threadIdx.x;
    for (int idx = tid; idx < GNN_HID * GNN_HID; idx += 256) sW2[idx] = W2[idx];
    if (tid < GNN_HID) { sW1[tid] = W1[tid]; sb1[tid] = b1[tid]; }
    __syncthreads();

    int w = tid >> 5;
    int lane = tid & 31;
    int node = blockIdx.x * 8 + w;
    if (node >= N_NODES) return;

    float dv = g_dinv[node];
    float u = dv * g_acc1[node];
    float v0 = fmaxf(u * sW1[lane] + sb1[lane], 0.0f);
    float v1 = fmaxf(u * sW1[lane + 32] + sb1[lane + 32], 0.0f);
    sX[w][lane] = v0;
    sX[w][lane + 32] = v1;
    __syncwarp();

    float a0 = 0.0f, a1 = 0.0f;
#pragma unroll 8
    for (int j = 0; j < GNN_HID; j++) {
        float xv = sX[w][j];
        a0 += xv * sW2[j * GNN_HID + lane];
        a1 += xv * sW2[j * GNN_HID + lane + 32];
    }
    float h0 = dv * a0, h1 = dv * a1;
    size_t base = (size_t)node * GNN_HID;
    g_h2s[base + lane] = h0;  g_h2s[base + lane + 32] = h1;
    g_acc2[base + lane] = h0; g_acc2[base + lane + 32] = h1;
}

// one warp per edge: acc2[col,:] += h2s[row,:]
__global__ void k_scat2(const int* __restrict__ ei) {
    int gt = blockIdx.x * blockDim.x + threadIdx.x;
    int w = gt >> 5;
    int lane = gt & 31;
    if (w >= N_EDGES) return;
    int r = ei[w];
    int c = ei[N_EDGES + w];
    size_t rb = (size_t)r * GNN_HID;
    size_t cb = (size_t)c * GNN_HID;
    float v0 = g_h2s[rb + lane];
    float v1 = g_h2s[rb + lane + 32];
    atomicAdd(&g_acc2[cb + lane], v0);
    atomicAdd(&g_acc2[cb + lane + 32], v1);
}

// x2 = relu(dinv*acc2 + b2), pooled sum+count (fused; x2 never materialized)
__global__ void k_pool(const float* __restrict__ b2, const int* __restrict__ batch) {
    int gt = blockIdx.x * blockDim.x + threadIdx.x;
    int i = gt >> 5;
    int lane = gt & 31;
    if (i >= N_NODES) return;
    int bg = batch[i];
    float dv = g_dinv[i];
    size_t ib = (size_t)i * GNN_HID;
    float v0 = fmaxf(dv * g_acc2[ib + lane] + b2[lane], 0.0f);
    float v1 = fmaxf(dv * g_acc2[ib + lane + 32] + b2[lane + 32], 0.0f);
    size_t pb = (size_t)bg * GNN_HID;
    atomicAdd(&g_pool[pb + lane], v0);
    atomicAdd(&g_pool[pb + lane + 32], v1);
    if (lane == 0) atomicAdd(&g_cnt[bg], 1.0f);
}

// g = (pool/max(cnt,1)) @ Wg + bg -> first 128 cols of g_comb
__global__ __launch_bounds__(128) void k_gemb(const float* __restrict__ Wg,
                                              const float* __restrict__ bg) {
    __shared__ float sp[GNN_HID];
    int b = blockIdx.x;
    int t = threadIdx.x;
    float inv = 1.0f / fmaxf(g_cnt[b], 1.0f);
    if (t < GNN_HID) sp[t] = g_pool[(size_t)b * GNN_HID + t] * inv;
    __syncthreads();
    float acc = bg[t];
#pragma unroll 8
    for (int j = 0; j < GNN_HID; j++) acc += sp[j] * Wg[j * G_EMB + t];
    g_comb[(size_t)b * KP + t] = acc;
}

// fill compound/protein/pad region of g_comb
__global__ void k_concat(const float* __restrict__ comp, const float* __restrict__ prot) {
    long long idx = (long long)blockIdx.x * blockDim.x + threadIdx.x;
    const int W = KP - G_EMB; // 3928
    if (idx >= (long long)N_GRAPHS * W) return;
    int b = (int)(idx / W);
    int c = (int)(idx % W) + G_EMB;
    float v;
    if (c < G_EMB + COMP_DIM)      v = comp[(size_t)b * COMP_DIM + (c - G_EMB)];
    else if (c < K_TOT)            v = prot[(size_t)b * PROT_DIM + (c - G_EMB - COMP_DIM)];
    else                           v = 0.0f;
    g_comb[(size_t)b * KP + c] = v;
}

__global__ void k_padW(const float* __restrict__ Wf1) {
    int idx = blockIdx.x * blockDim.x + threadIdx.x;
    if (idx >= KP * HID) return;
    int k = idx / HID;
    g_w1p[idx] = (k < K_TOT) ? Wf1[idx] : 0.0f;
}

// SGEMM: g_hid[16384,256] = relu(g_comb[16384,KP] @ g_w1p[KP,256] + bf1)
// BM=128 BN=64 BK=8, 256 threads, 8x4 register tile
__global__ __launch_bounds__(256) void k_gemm(const float* __restrict__ bf1) {
    __shared__ float As[8][128];
    __shared__ float Bs[8][64];
    int m0 = blockIdx.x * 128;
    int n0 = blockIdx.y * 64;
    int tid = threadIdx.x;
    int ty = tid >> 4;          // 0..15 -> 8 rows each
    int tx = tid & 15;          // 0..15 -> 4 cols each
    int lm = tid >> 1;          // A-load row 0..127
    int lk = (tid & 1) * 4;     // A-load k offset
    int bk = tid >> 5;          // B-load k 0..7
    int bn = (tid & 31) * 2;    // B-load n

    const float* Aptr = g_comb + (size_t)(m0 + lm) * KP;
    const float* Bptr = g_w1p + n0;

    float acc[8][4];
#pragma unroll
    for (int x = 0; x < 8; x++)
#pragma unroll
        for (int y = 0; y < 4; y++) acc[x][y] = 0.0f;

    for (int kt = 0; kt < KP; kt += 8) {
        float4 av = *(const float4*)(Aptr + kt + lk);
        As[lk + 0][lm] = av.x; As[lk + 1][lm] = av.y;
        As[lk + 2][lm] = av.z; As[lk + 3][lm] = av.w;
        float2 bv = *(const float2*)(Bptr + (size_t)(kt + bk) * HID + bn);
        Bs[bk][bn] = bv.x; Bs[bk][bn + 1] = bv.y;
        __syncthreads();
#pragma unroll
        for (int kk = 0; kk < 8; kk++) {
            float a[8], b[4];
#pragma unroll
            for (int x = 0; x < 8; x++) a[x] = As[kk][ty * 8 + x];
#pragma unroll
            for (int y = 0; y < 4; y++) b[y] = Bs[kk][tx * 4 + y];
#pragma unroll
            for (int x = 0; x < 8; x++)
#pragma unroll
                for (int y = 0; y < 4; y++) acc[x][y] += a[x] * b[y];
        }
        __syncthreads();
    }

#pragma unroll
    for (int x = 0; x < 8; x++) {
        int m = m0 + ty * 8 + x;
        int n = n0 + tx * 4;
        float4 o;
        o.x = fmaxf(acc[x][0] + bf1[n + 0], 0.0f);
        o.y = fmaxf(acc[x][1] + bf1[n + 1], 0.0f);
        o.z = fmaxf(acc[x][2] + bf1[n + 2], 0.0f);
        o.w = fmaxf(acc[x][3] + bf1[n + 3], 0.0f);
        *(float4*)(g_hid + (size_t)m * HID + n) = o;
    }
}

// out = sigmoid(g_hid @ Wf2 + bf2), one warp per graph
__global__ void k_final(const float* __restrict__ Wf2, const float* __restrict__ bf2,
                        float* __restrict__ out) {
    int gt = blockIdx.x * blockDim.x + threadIdx.x;
    int b = gt >> 5;
    int lane = gt & 31;
    if (b >= N_GRAPHS) return;
    float acc = 0.0f;
    size_t base = (size_t)b * HID;
#pragma unroll
    for (int o = lane; o < HID; o += 32) acc += g_hid[base + o] * Wf2[o];
#pragma unroll
    for (int s = 16; s > 0; s >>= 1) acc += __shfl_down_sync(0xFFFFFFFFu, acc, s);
    if (lane == 0) {
        float z = acc + bf2[0];
        out[b] = 1.0f / (1.0f + expf(-z));
    }
}

// -------------------- launch --------------------
extern "C" void kernel_launch(void* const* d_in, const int* in_sizes, int n_in,
                              void* d_out, int out_size) {
    const float* node_x = (const float*)d_in[0];
    const float* comp   = (const float*)d_in[1];
    const float* prot   = (const float*)d_in[2];
    const int*   ei     = (const int*)d_in[3];
    const int*   batch  = (const int*)d_in[4];
    const float* W1     = (const float*)d_in[5];
    const float* b1     = (const float*)d_in[6];
    const float* W2     = (const float*)d_in[7];
    const float* b2     = (const float*)d_in[8];
    const float* Wg     = (const float*)d_in[9];
    const float* bg     = (const float*)d_in[10];
    const float* Wf1    = (const float*)d_in[11];
    const float* bf1    = (const float*)d_in[12];
    const float* Wf2    = (const float*)d_in[13];
    const float* bf2    = (const float*)d_in[14];
    float* out = (float*)d_out;

    k_init<<<(INIT_N + 255) / 256, 256>>>();   // FIX: cover g_pool fully (was N_NODES)
    k_deg<<<(N_EDGES + 255) / 256, 256>>>(ei);
    k_dinv<<<(N_NODES + 255) / 256, 256>>>(node_x);
    k_scat1<<<(N_EDGES + 255) / 256, 256>>>(ei);
    k_layer2<<<N_NODES / 8, 256>>>(W1, b1, W2);
    k_scat2<<<(N_EDGES * 32) / 256, 256>>>(ei);
    k_pool<<<(N_NODES * 32) / 256, 256>>>(b2, batch);
    k_gemb<<<N_GRAPHS, 128>>>(Wg, bg);
    {
        long long tot = (long long)N_GRAPHS * (KP - G_EMB);
        k_concat<<<(unsigned)((tot + 255) / 256), 256>>>(comp, prot);
    }
    k_padW<<<(KP * HID + 255) / 256, 256>>>(Wf1);
    {
        dim3 grid(N_GRAPHS / 128, HID / 64);
        k_gemm<<<grid, 256>>>(bf1);
    }
    k_final<<<(N_GRAPHS * 32) / 256, 256>>>(Wf2, bf2, out);
}

// round 4
// speedup vs baseline: 1.8177x; 1.8177x over previous
#include <cuda_runtime.h>
#include <cuda_bf16.h>
#include <math.h>
#include <stdint.h>

#define N_NODES  524288
#define N_EDGES  2097152
#define N_GRAPHS 16384
#define COMP_DIM 3539
#define PROT_DIM 384
#define GNN_HID  64
#define G_EMB    128
#define HID      256
#define K_TOT    (G_EMB + COMP_DIM + PROT_DIM)   /* 4051 */
#define KP2      4096
#define INIT_N   (N_GRAPHS * GNN_HID)

// -------------------- scratch (static device memory; no allocs) --------------------
__device__ float g_dinv[N_NODES];
__device__ float g_s[N_NODES];
__device__ float g_acc1[N_NODES];
__device__ float g_h2s[N_NODES * GNN_HID];
__device__ float g_acc2[N_NODES * GNN_HID];
__device__ float g_pool[N_GRAPHS * GNN_HID];
__device__ float g_cnt[N_GRAPHS];
// bf16-split combined activations [16384,4096] and transposed weights [256,4096]
__device__ __nv_bfloat16 g_ah[(size_t)N_GRAPHS * KP2];
__device__ __nv_bfloat16 g_al[(size_t)N_GRAPHS * KP2];
__device__ __nv_bfloat16 g_wh[(size_t)HID * KP2];
__device__ __nv_bfloat16 g_wl[(size_t)HID * KP2];

// -------------------- helpers --------------------
__device__ __forceinline__ void split2(float v, __nv_bfloat16& h, __nv_bfloat16& l) {
    h = __float2bfloat16(v);
    l = __float2bfloat16(v - __bfloat162float(h));
}

__device__ __forceinline__ uint32_t s2u(const void* p) {
    uint32_t a;
    asm("{ .reg .u64 t; cvta.to.shared.u64 t, %1; cvt.u32.u64 %0, t; }" : "=r"(a) : "l"(p));
    return a;
}

#define CP16(dst, src) \
    asm volatile("cp.async.cg.shared.global [%0], [%1], 16;" :: "r"(dst), "l"(src) : "memory")

__device__ __forceinline__ void mma16816(float* c, const uint32_t* a, const uint32_t* b) {
    asm volatile(
        "mma.sync.aligned.m16n8k16.row.col.f32.bf16.bf16.f32 "
        "{%0,%1,%2,%3}, {%4,%5,%6,%7}, {%8,%9}, {%0,%1,%2,%3};"
        : "+f"(c[0]), "+f"(c[1]), "+f"(c[2]), "+f"(c[3])
        : "r"(a[0]), "r"(a[1]), "r"(a[2]), "r"(a[3]), "r"(b[0]), "r"(b[1]));
}

// -------------------- GEMM geometry --------------------
#define BM 128
#define BN 256
#define BK 32
#define NCHUNK (KP2 / BK)     /* 128 */
#define SKA 40                /* padded smem row stride, bf16 elems (80B) */
#define THR 512

// dynamic smem layout (bytes)
#define SZ_A   (128 * SKA * 2)     /* 10240 */
#define SZ_B   (256 * SKA * 2)     /* 20480 */
#define OFF_AH 0
#define OFF_AL (OFF_AH + SZ_A)
#define OFF_BH (OFF_AL + SZ_A)
#define OFF_BL (OFF_BH + SZ_B)
#define STAGE_SZ (OFF_BL + SZ_B)   /* 61440 */
#define OFF_BF1 (2 * STAGE_SZ)     /* 122880 */
#define OFF_WF2 (OFF_BF1 + 1024)
#define OFF_RED (OFF_WF2 + 1024)   /* 128*4 floats = 2048 */
#define SMEM_BYTES (OFF_RED + 2048) /* 126976 */

// -------------------- GNN kernels (numerics as in passing R2 kernel) --------------------

__global__ void k_init() {
    int i = blockIdx.x * blockDim.x + threadIdx.x;
    if (i < N_NODES) g_dinv[i] = 1.0f;
    if (i < N_GRAPHS * GNN_HID) g_pool[i] = 0.0f;
    if (i < N_GRAPHS) g_cnt[i] = 0.0f;
}

__global__ void k_deg(const int* __restrict__ ei) {
    int e = blockIdx.x * blockDim.x + threadIdx.x;
    if (e < N_EDGES) atomicAdd(&g_dinv[ei[N_EDGES + e]], 1.0f);
}

__global__ void k_dinv(const float* __restrict__ node_x) {
    int i = blockIdx.x * blockDim.x + threadIdx.x;
    if (i >= N_NODES) return;
    float d = rsqrtf(g_dinv[i]);
    g_dinv[i] = d;
    float s = d * node_x[i];
    g_s[i] = s;
    g_acc1[i] = s;
}

__global__ void k_scat1(const int* __restrict__ ei) {
    int e = blockIdx.x * blockDim.x + threadIdx.x;
    if (e < N_EDGES) {
        int r = ei[e];
        int c = ei[N_EDGES + e];
        atomicAdd(&g_acc1[c], g_s[r]);
    }
}

__global__ __launch_bounds__(256) void k_layer2(const float* __restrict__ W1,
                                                const float* __restrict__ b1,
                                                const float* __restrict__ W2) {
    __shared__ float sW2[GNN_HID * GNN_HID];
    __shared__ float sW1[GNN_HID];
    __shared__ float sb1[GNN_HID];
    __shared__ float sX[8][GNN_HID];

    int tid = threadIdx.x;
    for (int idx = tid; idx < GNN_HID * GNN_HID; idx += 256) sW2[idx] = W2[idx];
    if (tid < GNN_HID) { sW1[tid] = W1[tid]; sb1[tid] = b1[tid]; }
    __syncthreads();

    int w = tid >> 5;
    int lane = tid & 31;
    int node = blockIdx.x * 8 + w;
    if (node >= N_NODES) return;

    float dv = g_dinv[node];
    float u = dv * g_acc1[node];
    float v0 = fmaxf(u * sW1[lane] + sb1[lane], 0.0f);
    float v1 = fmaxf(u * sW1[lane + 32] + sb1[lane + 32], 0.0f);
    sX[w][lane] = v0;
    sX[w][lane + 32] = v1;
    __syncwarp();

    float a0 = 0.0f, a1 = 0.0f;
#pragma unroll 8
    for (int j = 0; j < GNN_HID; j++) {
        float xv = sX[w][j];
        a0 += xv * sW2[j * GNN_HID + lane];
        a1 += xv * sW2[j * GNN_HID + lane + 32];
    }
    float h0 = dv * a0, h1 = dv * a1;
    size_t base = (size_t)node * GNN_HID;
    g_h2s[base + lane] = h0;  g_h2s[base + lane + 32] = h1;
    g_acc2[base + lane] = h0; g_acc2[base + lane + 32] = h1;
}

__global__ void k_scat2(const int* __restrict__ ei) {
    int gt = blockIdx.x * blockDim.x + threadIdx.x;
    int w = gt >> 5;
    int lane = gt & 31;
    if (w >= N_EDGES) return;
    int r = ei[w];
    int c = ei[N_EDGES + w];
    size_t rb = (size_t)r * GNN_HID;
    size_t cb = (size_t)c * GNN_HID;
    float v0 = g_h2s[rb + lane];
    float v1 = g_h2s[rb + lane + 32];
    atomicAdd(&g_acc2[cb + lane], v0);
    atomicAdd(&g_acc2[cb + lane + 32], v1);
}

__global__ void k_pool(const float* __restrict__ b2, const int* __restrict__ batch) {
    int gt = blockIdx.x * blockDim.x + threadIdx.x;
    int i = gt >> 5;
    int lane = gt & 31;
    if (i >= N_NODES) return;
    int bg = batch[i];
    float dv = g_dinv[i];
    size_t ib = (size_t)i * GNN_HID;
    float v0 = fmaxf(dv * g_acc2[ib + lane] + b2[lane], 0.0f);
    float v1 = fmaxf(dv * g_acc2[ib + lane + 32] + b2[lane + 32], 0.0f);
    size_t pb = (size_t)bg * GNN_HID;
    atomicAdd(&g_pool[pb + lane], v0);
    atomicAdd(&g_pool[pb + lane + 32], v1);
    if (lane == 0) atomicAdd(&g_cnt[bg], 1.0f);
}

__global__ __launch_bounds__(128) void k_gemb(const float* __restrict__ Wg,
                                              const float* __restrict__ bg) {
    __shared__ float sp[GNN_HID];
    int b = blockIdx.x;
    int t = threadIdx.x;
    float inv = 1.0f / fmaxf(g_cnt[b], 1.0f);
    if (t < GNN_HID) sp[t] = g_pool[(size_t)b * GNN_HID + t] * inv;
    __syncthreads();
    float acc = bg[t];
#pragma unroll 8
    for (int j = 0; j < GNN_HID; j++) acc += sp[j] * Wg[j * G_EMB + t];
    __nv_bfloat16 h, l;
    split2(acc, h, l);
    size_t o = (size_t)b * KP2 + t;
    g_ah[o] = h;
    g_al[o] = l;
}

__global__ void k_concat(const float* __restrict__ comp, const float* __restrict__ prot) {
    long long idx = (long long)blockIdx.x * blockDim.x + threadIdx.x;
    const int W = KP2 - G_EMB; // 3968
    if (idx >= (long long)N_GRAPHS * W) return;
    int b = (int)(idx / W);
    int c = (int)(idx % W) + G_EMB;
    float v;
    if (c < G_EMB + COMP_DIM)      v = comp[(size_t)b * COMP_DIM + (c - G_EMB)];
    else if (c < K_TOT)            v = prot[(size_t)b * PROT_DIM + (c - G_EMB - COMP_DIM)];
    else                           v = 0.0f;
    __nv_bfloat16 h, l;
    split2(v, h, l);
    size_t o = (size_t)b * KP2 + c;
    g_ah[o] = h;
    g_al[o] = l;
}

// Wf1 [4051,256] -> transposed padded bf16 hi/lo [256][4096]
__global__ void k_padWt(const float* __restrict__ Wf1) {
    int idx = blockIdx.x * blockDim.x + threadIdx.x;
    if (idx >= HID * KP2) return;
    int n = idx / KP2;
    int k = idx % KP2;
    float v = (k < K_TOT) ? Wf1[(size_t)k * HID + n] : 0.0f;
    __nv_bfloat16 h, l;
    split2(v, h, l);
    g_wh[idx] = h;
    g_wl[idx] = l;
}

// -------------------- bf16 mma.sync GEMM + fused epilogue --------------------
// D[128,256] per CTA = Ah*Wh^T + Al*Wh^T + Ah*Wl^T (fp32 acc)
// out[m] = sigmoid(sum_n relu(D[m,n]+bf1[n])*Wf2[n] + bf2)

__device__ __forceinline__ void stage_loads(uint32_t sbase, int m0, int kt, int tid) {
    size_t kof = (size_t)kt * BK;
    {   // A: 128 rows x 4 x 16B segs = 512 -> 1 per thread (hi and lo)
        int r = tid >> 2, seg = tid & 3;
        uint32_t d = sbase + r * (SKA * 2) + seg * 16;
        const __nv_bfloat16* s = &g_ah[(size_t)(m0 + r) * KP2 + kof + seg * 8];
        CP16(d + OFF_AH, s);
        const __nv_bfloat16* s2 = &g_al[(size_t)(m0 + r) * KP2 + kof + seg * 8];
        CP16(d + OFF_AL, s2);
    }
#pragma unroll
    for (int it = 0; it < 2; it++) {  // B: 256 rows x 4 segs = 1024 -> 2 per thread
        int idx = tid + it * THR;
        int r = idx >> 2, seg = idx & 3;
        uint32_t d = sbase + r * (SKA * 2) + seg * 16;
        const __nv_bfloat16* s = &g_wh[(size_t)r * KP2 + kof + seg * 8];
        CP16(d + OFF_BH, s);
        const __nv_bfloat16* s2 = &g_wl[(size_t)r * KP2 + kof + seg * 8];
        CP16(d + OFF_BL, s2);
    }
}

__device__ __forceinline__ void load_afrag(uint32_t a[2][4], const char* As,
                                           int mw, int kc, int g, int tig) {
#pragma unroll
    for (int mt = 0; mt < 2; mt++) {
        int r0 = mw * 32 + mt * 16 + g;
        const char* p = As + (size_t)r0 * (SKA * 2) + (size_t)(kc + tig * 2) * 2;
        a[mt][0] = *(const uint32_t*)(p);
        a[mt][1] = *(const uint32_t*)(p + 8 * (SKA * 2));
        a[mt][2] = *(const uint32_t*)(p + 16);
        a[mt][3] = *(const uint32_t*)(p + 8 * (SKA * 2) + 16);
    }
}

__device__ __forceinline__ void load_bfrag(uint32_t b[8][2], const char* Bs,
                                           int nw, int kc, int g, int tig) {
#pragma unroll
    for (int nt = 0; nt < 8; nt++) {
        int n0 = nw * 64 + nt * 8 + g;
        const char* p = Bs + (size_t)n0 * (SKA * 2) + (size_t)(kc + tig * 2) * 2;
        b[nt][0] = *(const uint32_t*)(p);
        b[nt][1] = *(const uint32_t*)(p + 16);
    }
}

__device__ __forceinline__ void mma_all(float acc[2][8][4], uint32_t a[2][4], uint32_t b[8][2]) {
#pragma unroll
    for (int mt = 0; mt < 2; mt++)
#pragma unroll
        for (int nt = 0; nt < 8; nt++)
            mma16816(acc[mt][nt], a[mt], b[nt]);
}

__global__ void __launch_bounds__(THR, 1) k_gemm_mma(const float* __restrict__ bf1,
                                                     const float* __restrict__ Wf2,
                                                     const float* __restrict__ bf2,
                                                     float* __restrict__ out) {
    extern __shared__ char smem[];
    uint32_t sb = s2u(smem);
    int tid = threadIdx.x;
    int wid = tid >> 5, lane = tid & 31;
    int mw = wid >> 2, nw = wid & 3;
    int g = lane >> 2, tig = lane & 3;
    int m0 = blockIdx.x * BM;

    float* s_bf1 = (float*)(smem + OFF_BF1);
    float* s_wf2 = (float*)(smem + OFF_WF2);
    float* s_red = (float*)(smem + OFF_RED);
    if (tid < HID) { s_bf1[tid] = bf1[tid]; s_wf2[tid] = Wf2[tid]; }

    float acc[2][8][4];
#pragma unroll
    for (int mt = 0; mt < 2; mt++)
#pragma unroll
        for (int nt = 0; nt < 8; nt++)
#pragma unroll
            for (int e = 0; e < 4; e++) acc[mt][nt][e] = 0.0f;

    stage_loads(sb, m0, 0, tid);
    asm volatile("cp.async.commit_group;" ::: "memory");

    for (int i = 0; i < NCHUNK; i++) {
        const char* stg = smem + (i & 1) * STAGE_SZ;
        if (i + 1 < NCHUNK) {
            stage_loads(sb + ((i + 1) & 1) * STAGE_SZ, m0, i + 1, tid);
            asm volatile("cp.async.commit_group;" ::: "memory");
            asm volatile("cp.async.wait_group 1;" ::: "memory");
        } else {
            asm volatile("cp.async.wait_group 0;" ::: "memory");
        }
        __syncthreads();

        const char* Ah = stg + OFF_AH;
        const char* Al = stg + OFF_AL;
        const char* Bh = stg + OFF_BH;
        const char* Bl = stg + OFF_BL;
#pragma unroll
        for (int kk = 0; kk < 2; kk++) {
            int kc = kk * 16;
            uint32_t a[2][4], b[8][2];
            load_afrag(a, Ah, mw, kc, g, tig);
            load_bfrag(b, Bh, nw, kc, g, tig);
            mma_all(acc, a, b);             // Ah*Bh
            load_afrag(a, Al, mw, kc, g, tig);
            mma_all(acc, a, b);             // Al*Bh
            load_bfrag(b, Bl, nw, kc, g, tig);
            load_afrag(a, Ah, mw, kc, g, tig);
            mma_all(acc, a, b);             // Ah*Bl
        }
        __syncthreads();   // all warps done reading before this buffer is refilled
    }

    // fused epilogue: bias + relu + dot(Wf2) + cross-warp reduce + sigmoid
#pragma unroll
    for (int mt = 0; mt < 2; mt++) {
#pragma unroll
        for (int half = 0; half < 2; half++) {
            int rowl = mw * 32 + mt * 16 + half * 8 + g;
            float p = 0.0f;
#pragma unroll
            for (int nt = 0; nt < 8; nt++) {
                int col = nw * 64 + nt * 8 + tig * 2;
                float v0 = fmaxf(acc[mt][nt][half * 2 + 0] + s_bf1[col], 0.0f);
                float v1 = fmaxf(acc[mt][nt][half * 2 + 1] + s_bf1[col + 1], 0.0f);
                p = fmaf(v0, s_wf2[col], p);
                p = fmaf(v1, s_wf2[col + 1], p);
            }
            p += __shfl_xor_sync(0xFFFFFFFFu, p, 1);
            p += __shfl_xor_sync(0xFFFFFFFFu, p, 2);
            if (tig == 0) s_red[rowl * 4 + nw] = p;
        }
    }
    __syncthreads();
    if (tid < BM) {
        float z = s_red[tid * 4] + s_red[tid * 4 + 1] + s_red[tid * 4 + 2] +
                  s_red[tid * 4 + 3] + bf2[0];
        out[m0 + tid] = 1.0f / (1.0f + expf(-z));
    }
}

// -------------------- launch --------------------
extern "C" void kernel_launch(void* const* d_in, const int* in_sizes, int n_in,
                              void* d_out, int out_size) {
    const float* node_x = (const float*)d_in[0];
    const float* comp   = (const float*)d_in[1];
    const float* prot   = (const float*)d_in[2];
    const int*   ei     = (const int*)d_in[3];
    const int*   batch  = (const int*)d_in[4];
    const float* W1     = (const float*)d_in[5];
    const float* b1     = (const float*)d_in[6];
    const float* W2     = (const float*)d_in[7];
    const float* b2     = (const float*)d_in[8];
    const float* Wg     = (const float*)d_in[9];
    const float* bg     = (const float*)d_in[10];
    const float* Wf1    = (const float*)d_in[11];
    const float* bf1    = (const float*)d_in[12];
    const float* Wf2    = (const float*)d_in[13];
    const float* bf2    = (const float*)d_in[14];
    float* out = (float*)d_out;

    k_init<<<(INIT_N + 255) / 256, 256>>>();
    k_deg<<<(N_EDGES + 255) / 256, 256>>>(ei);
    k_dinv<<<(N_NODES + 255) / 256, 256>>>(node_x);
    k_scat1<<<(N_EDGES + 255) / 256, 256>>>(ei);
    k_layer2<<<N_NODES / 8, 256>>>(W1, b1, W2);
    k_scat2<<<(N_EDGES * 32) / 256, 256>>>(ei);
    k_pool<<<(N_NODES * 32) / 256, 256>>>(b2, batch);
    k_gemb<<<N_GRAPHS, 128>>>(Wg, bg);
    {
        long long tot = (long long)N_GRAPHS * (KP2 - G_EMB);
        k_concat<<<(unsigned)((tot + 255) / 256), 256>>>(comp, prot);
    }
    k_padWt<<<(HID * KP2 + 255) / 256, 256>>>(Wf1);

    cudaFuncSetAttribute(k_gemm_mma, cudaFuncAttributeMaxDynamicSharedMemorySize, SMEM_BYTES);
    k_gemm_mma<<<N_GRAPHS / BM, THR, SMEM_BYTES>>>(bf1, Wf2, bf2, out);
}

// round 5
// speedup vs baseline: 2.0751x; 1.1416x over previous
#include <cuda_runtime.h>
#include <cuda_bf16.h>
#include <math.h>
#include <stdint.h>

#define N_NODES  524288
#define N_EDGES  2097152
#define N_GRAPHS 16384
#define COMP_DIM 3539
#define PROT_DIM 384
#define GNN_HID  64
#define G_EMB    128
#define HID      256
#define K_TOT    (G_EMB + COMP_DIM + PROT_DIM)   /* 4051 */
#define KP2      4096
#define INIT_N   (N_GRAPHS * GNN_HID)

#define SCAN_BLK   1024
#define NSCAN_BLKS (N_NODES / SCAN_BLK)   /* 512 */

// -------------------- scratch (static device memory; no allocs) --------------------
__device__ float g_dinv[N_NODES];
__device__ float g_s[N_NODES];
__device__ float g_acc1[N_NODES];
__device__ float g_h2s[N_NODES * GNN_HID];
__device__ float g_pool[N_GRAPHS * GNN_HID];
__device__ float g_cnt[N_GRAPHS];
// edge bucketing (counting sort by destination)
__device__ int g_ecnt[N_NODES];
__device__ int g_eoff[N_NODES];
__device__ int g_cur[N_NODES];
__device__ int g_bsum[NSCAN_BLKS];
__device__ int g_erow[N_EDGES];
// bf16-split combined activations [16384,4096] and transposed weights [256,4096]
__device__ __nv_bfloat16 g_ah[(size_t)N_GRAPHS * KP2];
__device__ __nv_bfloat16 g_al[(size_t)N_GRAPHS * KP2];
__device__ __nv_bfloat16 g_wh[(size_t)HID * KP2];
__device__ __nv_bfloat16 g_wl[(size_t)HID * KP2];

// -------------------- helpers --------------------
__device__ __forceinline__ void split2(float v, __nv_bfloat16& h, __nv_bfloat16& l) {
    h = __float2bfloat16(v);
    l = __float2bfloat16(v - __bfloat162float(h));
}

__device__ __forceinline__ uint32_t s2u(const void* p) {
    uint32_t a;
    asm("{ .reg .u64 t; cvta.to.shared.u64 t, %1; cvt.u32.u64 %0, t; }" : "=r"(a) : "l"(p));
    return a;
}

#define CP16(dst, src) \
    asm volatile("cp.async.cg.shared.global [%0], [%1], 16;" :: "r"(dst), "l"(src) : "memory")

__device__ __forceinline__ void mma16816(float* c, const uint32_t* a, const uint32_t* b) {
    asm volatile(
        "mma.sync.aligned.m16n8k16.row.col.f32.bf16.bf16.f32 "
        "{%0,%1,%2,%3}, {%4,%5,%6,%7}, {%8,%9}, {%0,%1,%2,%3};"
        : "+f"(c[0]), "+f"(c[1]), "+f"(c[2]), "+f"(c[3])
        : "r"(a[0]), "r"(a[1]), "r"(a[2]), "r"(a[3]), "r"(b[0]), "r"(b[1]));
}

// -------------------- GEMM geometry --------------------
#define BM 128
#define BN 256
#define BK 32
#define NCHUNK (KP2 / BK)     /* 128 */
#define SKA 40                /* padded smem row stride, bf16 elems (80B) */
#define THR 512

#define SZ_A   (128 * SKA * 2)
#define SZ_B   (256 * SKA * 2)
#define OFF_AH 0
#define OFF_AL (OFF_AH + SZ_A)
#define OFF_BH (OFF_AL + SZ_A)
#define OFF_BL (OFF_BH + SZ_B)
#define STAGE_SZ (OFF_BL + SZ_B)
#define OFF_BF1 (2 * STAGE_SZ)
#define OFF_WF2 (OFF_BF1 + 1024)
#define OFF_RED (OFF_WF2 + 1024)
#define SMEM_BYTES (OFF_RED + 2048)

// -------------------- setup / bucketing kernels --------------------

__global__ void k_init() {
    int i = blockIdx.x * blockDim.x + threadIdx.x;
    if (i < N_NODES) g_ecnt[i] = 0;
    if (i < N_GRAPHS * GNN_HID) g_pool[i] = 0.0f;
    if (i < N_GRAPHS) g_cnt[i] = 0.0f;
}

__global__ void k_hist(const int* __restrict__ ei) {
    int e = blockIdx.x * blockDim.x + threadIdx.x;
    if (e < N_EDGES) atomicAdd(&g_ecnt[ei[N_EDGES + e]], 1);
}

__global__ __launch_bounds__(SCAN_BLK) void k_scan1() {
    __shared__ int sh[SCAN_BLK];
    int t = threadIdx.x;
    int base = blockIdx.x * SCAN_BLK;
    int v = g_ecnt[base + t];
    sh[t] = v;
    __syncthreads();
#pragma unroll
    for (int off = 1; off < SCAN_BLK; off <<= 1) {
        int x = (t >= off) ? sh[t - off] : 0;
        __syncthreads();
        sh[t] += x;
        __syncthreads();
    }
    g_eoff[base + t] = sh[t] - v;   // exclusive within block
    if (t == SCAN_BLK - 1) g_bsum[blockIdx.x] = sh[t];
}

__global__ __launch_bounds__(NSCAN_BLKS) void k_scan2() {
    __shared__ int sh[NSCAN_BLKS];
    int t = threadIdx.x;
    int v = g_bsum[t];
    sh[t] = v;
    __syncthreads();
#pragma unroll
    for (int off = 1; off < NSCAN_BLKS; off <<= 1) {
        int x = (t >= off) ? sh[t - off] : 0;
        __syncthreads();
        sh[t] += x;
        __syncthreads();
    }
    g_bsum[t] = sh[t] - v;          // exclusive block offsets
}

__global__ __launch_bounds__(SCAN_BLK) void k_scan3() {
    int i = blockIdx.x * SCAN_BLK + threadIdx.x;
    int o = g_eoff[i] + g_bsum[blockIdx.x];
    g_eoff[i] = o;
    g_cur[i] = o;
}

__global__ void k_bucket(const int* __restrict__ ei) {
    int e = blockIdx.x * blockDim.x + threadIdx.x;
    if (e < N_EDGES) {
        int c = ei[N_EDGES + e];
        int pos = atomicAdd(&g_cur[c], 1);
        g_erow[pos] = ei[e];
    }
}

__global__ void k_dinv(const float* __restrict__ node_x) {
    int i = blockIdx.x * blockDim.x + threadIdx.x;
    if (i >= N_NODES) return;
    float d = rsqrtf(1.0f + (float)g_ecnt[i]);   // deg incl. self-loop
    g_dinv[i] = d;
    float s = d * node_x[i];
    g_s[i] = s;
    g_acc1[i] = s;                               // self-loop contribution
}

__global__ void k_scat1(const int* __restrict__ ei) {
    int e = blockIdx.x * blockDim.x + threadIdx.x;
    if (e < N_EDGES) {
        int r = ei[e];
        int c = ei[N_EDGES + e];
        atomicAdd(&g_acc1[c], g_s[r]);
    }
}

// Fused: x1 = relu(dinv*acc1*W1 + b1) ; h2s = dinv * (x1 @ W2)
__global__ __launch_bounds__(256) void k_layer2(const float* __restrict__ W1,
                                                const float* __restrict__ b1,
                                                const float* __restrict__ W2) {
    __shared__ float sW2[GNN_HID * GNN_HID];
    __shared__ float sW1[GNN_HID];
    __shared__ float sb1[GNN_HID];
    __shared__ float sX[8][GNN_HID];

    int tid = threadIdx.x;
    for (int idx = tid; idx < GNN_HID * GNN_HID; idx += 256) sW2[idx] = W2[idx];
    if (tid < GNN_HID) { sW1[tid] = W1[tid]; sb1[tid] = b1[tid]; }
    __syncthreads();

    int w = tid >> 5;
    int lane = tid & 31;
    int node = blockIdx.x * 8 + w;
    if (node >= N_NODES) return;

    float dv = g_dinv[node];
    float u = dv * g_acc1[node];
    float v0 = fmaxf(u * sW1[lane] + sb1[lane], 0.0f);
    float v1 = fmaxf(u * sW1[lane + 32] + sb1[lane + 32], 0.0f);
    sX[w][lane] = v0;
    sX[w][lane + 32] = v1;
    __syncwarp();

    float a0 = 0.0f, a1 = 0.0f;
#pragma unroll 8
    for (int j = 0; j < GNN_HID; j++) {
        float xv = sX[w][j];
        a0 += xv * sW2[j * GNN_HID + lane];
        a1 += xv * sW2[j * GNN_HID + lane + 32];
    }
    size_t base = (size_t)node * GNN_HID;
    g_h2s[base + lane] = dv * a0;
    g_h2s[base + lane + 32] = dv * a1;
}

// Fused gather (layer-2 aggregation) + relu + mean-pool accumulation.
// One warp per node; neighbor indices preloaded coalesced, shfl-broadcast.
__global__ void k_gather(const float* __restrict__ b2, const int* __restrict__ batch) {
    int gt = blockIdx.x * blockDim.x + threadIdx.x;
    int node = gt >> 5;
    int lane = gt & 31;
    if (node >= N_NODES) return;

    int start = g_eoff[node];
    int cnt = g_ecnt[node];
    size_t sb = (size_t)node * GNN_HID;
    float a0 = g_h2s[sb + lane];          // self-loop term
    float a1 = g_h2s[sb + lane + 32];

    for (int base = 0; base < cnt; base += 32) {
        int n = min(32, cnt - base);
        int myidx = (base + lane < cnt) ? g_erow[start + base + lane] : 0;
#pragma unroll 4
        for (int j = 0; j < n; j++) {
            int r = __shfl_sync(0xFFFFFFFFu, myidx, j);
            size_t rb = (size_t)r * GNN_HID;
            a0 += g_h2s[rb + lane];
            a1 += g_h2s[rb + lane + 32];
        }
    }

    float dv = g_dinv[node];
    float v0 = fmaxf(dv * a0 + __ldg(&b2[lane]), 0.0f);
    float v1 = fmaxf(dv * a1 + __ldg(&b2[lane + 32]), 0.0f);
    int bg = batch[node];
    size_t pb = (size_t)bg * GNN_HID;
    atomicAdd(&g_pool[pb + lane], v0);
    atomicAdd(&g_pool[pb + lane + 32], v1);
    if (lane == 0) atomicAdd(&g_cnt[bg], 1.0f);
}

// g-embedding -> bf16 hi/lo into cols [0,128)
__global__ __launch_bounds__(128) void k_gemb(const float* __restrict__ Wg,
                                              const float* __restrict__ bg) {
    __shared__ float sp[GNN_HID];
    int b = blockIdx.x;
    int t = threadIdx.x;
    float inv = 1.0f / fmaxf(g_cnt[b], 1.0f);
    if (t < GNN_HID) sp[t] = g_pool[(size_t)b * GNN_HID + t] * inv;
    __syncthreads();
    float acc = bg[t];
#pragma unroll 8
    for (int j = 0; j < GNN_HID; j++) acc += sp[j] * Wg[j * G_EMB + t];
    __nv_bfloat16 h, l;
    split2(acc, h, l);
    size_t o = (size_t)b * KP2 + t;
    g_ah[o] = h;
    g_al[o] = l;
}

__global__ void k_concat(const float* __restrict__ comp, const float* __restrict__ prot) {
    long long idx = (long long)blockIdx.x * blockDim.x + threadIdx.x;
    const int W = KP2 - G_EMB; // 3968
    if (idx >= (long long)N_GRAPHS * W) return;
    int b = (int)(idx / W);
    int c = (int)(idx % W) + G_EMB;
    float v;
    if (c < G_EMB + COMP_DIM)      v = comp[(size_t)b * COMP_DIM + (c - G_EMB)];
    else if (c < K_TOT)            v = prot[(size_t)b * PROT_DIM + (c - G_EMB - COMP_DIM)];
    else                           v = 0.0f;
    __nv_bfloat16 h, l;
    split2(v, h, l);
    size_t o = (size_t)b * KP2 + c;
    g_ah[o] = h;
    g_al[o] = l;
}

__global__ void k_padWt(const float* __restrict__ Wf1) {
    int idx = blockIdx.x * blockDim.x + threadIdx.x;
    if (idx >= HID * KP2) return;
    int n = idx / KP2;
    int k = idx % KP2;
    float v = (k < K_TOT) ? Wf1[(size_t)k * HID + n] : 0.0f;
    __nv_bfloat16 h, l;
    split2(v, h, l);
    g_wh[idx] = h;
    g_wl[idx] = l;
}

// -------------------- bf16 mma.sync GEMM + fused epilogue --------------------

__device__ __forceinline__ void stage_loads(uint32_t sbase, int m0, int kt, int tid) {
    size_t kof = (size_t)kt * BK;
    {
        int r = tid >> 2, seg = tid & 3;
        uint32_t d = sbase + r * (SKA * 2) + seg * 16;
        const __nv_bfloat16* s = &g_ah[(size_t)(m0 + r) * KP2 + kof + seg * 8];
        CP16(d + OFF_AH, s);
        const __nv_bfloat16* s2 = &g_al[(size_t)(m0 + r) * KP2 + kof + seg * 8];
        CP16(d + OFF_AL, s2);
    }
#pragma unroll
    for (int it = 0; it < 2; it++) {
        int idx = tid + it * THR;
        int r = idx >> 2, seg = idx & 3;
        uint32_t d = sbase + r * (SKA * 2) + seg * 16;
        const __nv_bfloat16* s = &g_wh[(size_t)r * KP2 + kof + seg * 8];
        CP16(d + OFF_BH, s);
        const __nv_bfloat16* s2 = &g_wl[(size_t)r * KP2 + kof + seg * 8];
        CP16(d + OFF_BL, s2);
    }
}

__device__ __forceinline__ void load_afrag(uint32_t a[2][4], const char* As,
                                           int mw, int kc, int g, int tig) {
#pragma unroll
    for (int mt = 0; mt < 2; mt++) {
        int r0 = mw * 32 + mt * 16 + g;
        const char* p = As + (size_t)r0 * (SKA * 2) + (size_t)(kc + tig * 2) * 2;
        a[mt][0] = *(const uint32_t*)(p);
        a[mt][1] = *(const uint32_t*)(p + 8 * (SKA * 2));
        a[mt][2] = *(const uint32_t*)(p + 16);
        a[mt][3] = *(const uint32_t*)(p + 8 * (SKA * 2) + 16);
    }
}

__device__ __forceinline__ void load_bfrag(uint32_t b[8][2], const char* Bs,
                                           int nw, int kc, int g, int tig) {
#pragma unroll
    for (int nt = 0; nt < 8; nt++) {
        int n0 = nw * 64 + nt * 8 + g;
        const char* p = Bs + (size_t)n0 * (SKA * 2) + (size_t)(kc + tig * 2) * 2;
        b[nt][0] = *(const uint32_t*)(p);
        b[nt][1] = *(const uint32_t*)(p + 16);
    }
}

__device__ __forceinline__ void mma_all(float acc[2][8][4], uint32_t a[2][4], uint32_t b[8][2]) {
#pragma unroll
    for (int mt = 0; mt < 2; mt++)
#pragma unroll
        for (int nt = 0; nt < 8; nt++)
            mma16816(acc[mt][nt], a[mt], b[nt]);
}

__global__ void __launch_bounds__(THR, 1) k_gemm_mma(const float* __restrict__ bf1,
                                                     const float* __restrict__ Wf2,
                                                     const float* __restrict__ bf2,
                                                     float* __restrict__ out) {
    extern __shared__ char smem[];
    uint32_t sb = s2u(smem);
    int tid = threadIdx.x;
    int wid = tid >> 5, lane = tid & 31;
    int mw = wid >> 2, nw = wid & 3;
    int g = lane >> 2, tig = lane & 3;
    int m0 = blockIdx.x * BM;

    float* s_bf1 = (float*)(smem + OFF_BF1);
    float* s_wf2 = (float*)(smem + OFF_WF2);
    float* s_red = (float*)(smem + OFF_RED);
    if (tid < HID) { s_bf1[tid] = bf1[tid]; s_wf2[tid] = Wf2[tid]; }

    float acc[2][8][4];
#pragma unroll
    for (int mt = 0; mt < 2; mt++)
#pragma unroll
        for (int nt = 0; nt < 8; nt++)
#pragma unroll
            for (int e = 0; e < 4; e++) acc[mt][nt][e] = 0.0f;

    stage_loads(sb, m0, 0, tid);
    asm volatile("cp.async.commit_group;" ::: "memory");

    for (int i = 0; i < NCHUNK; i++) {
        const char* stg = smem + (i & 1) * STAGE_SZ;
        if (i + 1 < NCHUNK) {
            stage_loads(sb + ((i + 1) & 1) * STAGE_SZ, m0, i + 1, tid);
            asm volatile("cp.async.commit_group;" ::: "memory");
            asm volatile("cp.async.wait_group 1;" ::: "memory");
        } else {
            asm volatile("cp.async.wait_group 0;" ::: "memory");
        }
        __syncthreads();

        const char* Ah = stg + OFF_AH;
        const char* Al = stg + OFF_AL;
        const char* Bh = stg + OFF_BH;
        const char* Bl = stg + OFF_BL;
#pragma unroll
        for (int kk = 0; kk < 2; kk++) {
            int kc = kk * 16;
            uint32_t a[2][4], b[8][2];
            load_afrag(a, Ah, mw, kc, g, tig);
            load_bfrag(b, Bh, nw, kc, g, tig);
            mma_all(acc, a, b);             // Ah*Bh
            load_afrag(a, Al, mw, kc, g, tig);
            mma_all(acc, a, b);             // Al*Bh
            load_bfrag(b, Bl, nw, kc, g, tig);
            load_afrag(a, Ah, mw, kc, g, tig);
            mma_all(acc, a, b);             // Ah*Bl
        }
        __syncthreads();
    }

#pragma unroll
    for (int mt = 0; mt < 2; mt++) {
#pragma unroll
        for (int half = 0; half < 2; half++) {
            int rowl = mw * 32 + mt * 16 + half * 8 + g;
            float p = 0.0f;
#pragma unroll
            for (int nt = 0; nt < 8; nt++) {
                int col = nw * 64 + nt * 8 + tig * 2;
                float v0 = fmaxf(acc[mt][nt][half * 2 + 0] + s_bf1[col], 0.0f);
                float v1 = fmaxf(acc[mt][nt][half * 2 + 1] + s_bf1[col + 1], 0.0f);
                p = fmaf(v0, s_wf2[col], p);
                p = fmaf(v1, s_wf2[col + 1], p);
            }
            p += __shfl_xor_sync(0xFFFFFFFFu, p, 1);
            p += __shfl_xor_sync(0xFFFFFFFFu, p, 2);
            if (tig == 0) s_red[rowl * 4 + nw] = p;
        }
    }
    __syncthreads();
    if (tid < BM) {
        float z = s_red[tid * 4] + s_red[tid * 4 + 1] + s_red[tid * 4 + 2] +
                  s_red[tid * 4 + 3] + bf2[0];
        out[m0 + tid] = 1.0f / (1.0f + expf(-z));
    }
}

// -------------------- launch --------------------
extern "C" void kernel_launch(void* const* d_in, const int* in_sizes, int n_in,
                              void* d_out, int out_size) {
    const float* node_x = (const float*)d_in[0];
    const float* comp   = (const float*)d_in[1];
    const float* prot   = (const float*)d_in[2];
    const int*   ei     = (const int*)d_in[3];
    const int*   batch  = (const int*)d_in[4];
    const float* W1     = (const float*)d_in[5];
    const float* b1     = (const float*)d_in[6];
    const float* W2     = (const float*)d_in[7];
    const float* b2     = (const float*)d_in[8];
    const float* Wg     = (const float*)d_in[9];
    const float* bg     = (const float*)d_in[10];
    const float* Wf1    = (const float*)d_in[11];
    const float* bf1    = (const float*)d_in[12];
    const float* Wf2    = (const float*)d_in[13];
    const float* bf2    = (const float*)d_in[14];
    float* out = (float*)d_out;

    k_init<<<(INIT_N + 255) / 256, 256>>>();
    k_hist<<<(N_EDGES + 255) / 256, 256>>>(ei);
    k_scan1<<<NSCAN_BLKS, SCAN_BLK>>>();
    k_scan2<<<1, NSCAN_BLKS>>>();
    k_scan3<<<NSCAN_BLKS, SCAN_BLK>>>();
    k_bucket<<<(N_EDGES + 255) / 256, 256>>>(ei);
    k_dinv<<<(N_NODES + 255) / 256, 256>>>(node_x);
    k_scat1<<<(N_EDGES + 255) / 256, 256>>>(ei);
    k_layer2<<<N_NODES / 8, 256>>>(W1, b1, W2);
    k_gather<<<(N_NODES * 32) / 256, 256>>>(b2, batch);
    k_gemb<<<N_GRAPHS, 128>>>(Wg, bg);
    {
        long long tot = (long long)N_GRAPHS * (KP2 - G_EMB);
        k_concat<<<(unsigned)((tot + 255) / 256), 256>>>(comp, prot);
    }
    k_padWt<<<(HID * KP2 + 255) / 256, 256>>>(Wf1);

    cudaFuncSetAttribute(k_gemm_mma, cudaFuncAttributeMaxDynamicSharedMemorySize, SMEM_BYTES);
    k_gemm_mma<<<N_GRAPHS / BM, THR, SMEM_BYTES>>>(bf1, Wf2, bf2, out);
}